// round 3
// baseline (speedup 1.0000x reference)
#include <cuda_runtime.h>

// FeedForwardQuantum: out = relu(cos(x+theta) @ W1 + b1) @ W2 + b2
// x: [524288, 8] fp32, W1: [8,32], W2: [32,8].
// R2 finding: fma pipe at 44% = exactly the required FFMA2 cycles -> kernel is
// issue/latency bound (issue 47.5%, occ 25.8%, 84 regs -> 6 blocks/SM, ragged wave).
// R3: launch_bounds(128,7) for 7 blocks/SM + single wave; GEMM1 chains split 2-way
// for ILP; tighter reg usage.

#define EDIM 8
#define FDIM 32
#define RPT 4      // rows per thread (two f32x2 pairs)
#define BLOCK 128

struct CW {
    float4 wf[FDIM * 4];  // per f: [w1col e0-3][w1col e4-7][w2row e0-3][w2row e4-7]
    float  b1[FDIM];
    float  b2[EDIM];
};

__constant__ CW c_w;     // read by main kernel via constant port
__device__   CW g_s;     // scratch filled by prep kernel, memcpy'd into c_w

// packed f32x2 ops
__device__ __forceinline__ float2 ffma2(float2 a, float2 b, float2 c) {
    float2 d;
    asm("{\n\t"
        ".reg .b64 ra, rb, rc, rd;\n\t"
        "mov.b64 ra, {%2, %3};\n\t"
        "mov.b64 rb, {%4, %5};\n\t"
        "mov.b64 rc, {%6, %7};\n\t"
        "fma.rn.f32x2 rd, ra, rb, rc;\n\t"
        "mov.b64 {%0, %1}, rd;\n\t"
        "}"
        : "=f"(d.x), "=f"(d.y)
        : "f"(a.x), "f"(a.y), "f"(b.x), "f"(b.y), "f"(c.x), "f"(c.y));
    return d;
}
__device__ __forceinline__ float2 fmul2(float2 a, float2 b) {
    float2 d;
    asm("{\n\t"
        ".reg .b64 ra, rb, rd;\n\t"
        "mov.b64 ra, {%2, %3};\n\t"
        "mov.b64 rb, {%4, %5};\n\t"
        "mul.rn.f32x2 rd, ra, rb;\n\t"
        "mov.b64 {%0, %1}, rd;\n\t"
        "}"
        : "=f"(d.x), "=f"(d.y)
        : "f"(a.x), "f"(a.y), "f"(b.x), "f"(b.y));
    return d;
}
__device__ __forceinline__ float2 fadd2(float2 a, float2 b) {
    float2 d;
    asm("{\n\t"
        ".reg .b64 ra, rb, rd;\n\t"
        "mov.b64 ra, {%2, %3};\n\t"
        "mov.b64 rb, {%4, %5};\n\t"
        "add.rn.f32x2 rd, ra, rb;\n\t"
        "mov.b64 {%0, %1}, rd;\n\t"
        "}"
        : "=f"(d.x), "=f"(d.y)
        : "f"(a.x), "f"(a.y), "f"(b.x), "f"(b.y));
    return d;
}
__device__ __forceinline__ float2 dup2(float v) { return make_float2(v, v); }

// accurate-enough cos for |a| <~ 16: 2-term 2pi reduction + MUFU cos
__device__ __forceinline__ float fast_cos(float a) {
    const float INV_2PI = 0.15915494309189535f;
    const float PI2_HI  = 6.28318548202514648f;
    const float PI2_LO  = 1.7484555e-7f;
    float k = rintf(a * INV_2PI);
    float r = fmaf(k, -PI2_HI, a);
    r = fmaf(k, PI2_LO, r);
    return __cosf(r);
}

__global__ void ffq_prep(const float* __restrict__ w1, const float* __restrict__ b1,
                         const float* __restrict__ w2, const float* __restrict__ b2)
{
    int f = threadIdx.x;
    if (f < FDIM) {
        g_s.wf[f * 4 + 0] = make_float4(w1[0 * FDIM + f], w1[1 * FDIM + f],
                                        w1[2 * FDIM + f], w1[3 * FDIM + f]);
        g_s.wf[f * 4 + 1] = make_float4(w1[4 * FDIM + f], w1[5 * FDIM + f],
                                        w1[6 * FDIM + f], w1[7 * FDIM + f]);
        const float4* w2v = reinterpret_cast<const float4*>(w2);
        g_s.wf[f * 4 + 2] = w2v[f * 2 + 0];
        g_s.wf[f * 4 + 3] = w2v[f * 2 + 1];
        g_s.b1[f] = b1[f];
        if (f < EDIM) g_s.b2[f] = b2[f];
    }
}

__global__ void __launch_bounds__(BLOCK, 7)
ffq_kernel(const float* __restrict__ x, const float* __restrict__ theta,
           float* __restrict__ out, long long nrows)
{
    const int t = threadIdx.x;
    const long long idx  = (long long)blockIdx.x * BLOCK + t;
    const long long row0 = idx * RPT;
    if (row0 >= nrows) return;

    float th[EDIM];
#pragma unroll
    for (int e = 0; e < EDIM; e++) th[e] = __ldg(theta + e);

    if (row0 + RPT <= nrows) {
        // ---- fast path: 4 full rows; q packed as (row_i, row_j) f32x2 pairs ----
        const float4* xp = reinterpret_cast<const float4*>(x + row0 * EDIM);
        float2 q01[EDIM], q23[EDIM];
        {
            float4 a0 = xp[0], a1 = xp[1];   // row 0
            float4 b0 = xp[2], b1v = xp[3];  // row 1
            q01[0] = make_float2(fast_cos(a0.x + th[0]), fast_cos(b0.x + th[0]));
            q01[1] = make_float2(fast_cos(a0.y + th[1]), fast_cos(b0.y + th[1]));
            q01[2] = make_float2(fast_cos(a0.z + th[2]), fast_cos(b0.z + th[2]));
            q01[3] = make_float2(fast_cos(a0.w + th[3]), fast_cos(b0.w + th[3]));
            q01[4] = make_float2(fast_cos(a1.x + th[4]), fast_cos(b1v.x + th[4]));
            q01[5] = make_float2(fast_cos(a1.y + th[5]), fast_cos(b1v.y + th[5]));
            q01[6] = make_float2(fast_cos(a1.z + th[6]), fast_cos(b1v.z + th[6]));
            q01[7] = make_float2(fast_cos(a1.w + th[7]), fast_cos(b1v.w + th[7]));
        }
        {
            float4 a0 = xp[4], a1 = xp[5];   // row 2
            float4 b0 = xp[6], b1v = xp[7];  // row 3
            q23[0] = make_float2(fast_cos(a0.x + th[0]), fast_cos(b0.x + th[0]));
            q23[1] = make_float2(fast_cos(a0.y + th[1]), fast_cos(b0.y + th[1]));
            q23[2] = make_float2(fast_cos(a0.z + th[2]), fast_cos(b0.z + th[2]));
            q23[3] = make_float2(fast_cos(a0.w + th[3]), fast_cos(b0.w + th[3]));
            q23[4] = make_float2(fast_cos(a1.x + th[4]), fast_cos(b1v.x + th[4]));
            q23[5] = make_float2(fast_cos(a1.y + th[5]), fast_cos(b1v.y + th[5]));
            q23[6] = make_float2(fast_cos(a1.z + th[6]), fast_cos(b1v.z + th[6]));
            q23[7] = make_float2(fast_cos(a1.w + th[7]), fast_cos(b1v.w + th[7]));
        }

        float2 acc01[EDIM], acc23[EDIM];
#pragma unroll
        for (int e = 0; e < EDIM; e++) {
            float b = c_w.b2[e];
            acc01[e] = make_float2(b, b);
            acc23[e] = make_float2(b, b);
        }

#pragma unroll
        for (int f = 0; f < FDIM; f++) {
            float4 wa = c_w.wf[f * 4 + 0];   // w1[e0..3][f]
            float4 wb = c_w.wf[f * 4 + 1];   // w1[e4..7][f]
            float  bf = c_w.b1[f];
            float2 bfp = dup2(bf);

            // 2-way split chains (depth 4+join instead of 8)
            float2 h01a = ffma2(q01[0], dup2(wa.x), bfp);
            float2 h01b = fmul2(q01[1], dup2(wa.y));
            float2 h23a = ffma2(q23[0], dup2(wa.x), bfp);
            float2 h23b = fmul2(q23[1], dup2(wa.y));
            h01a = ffma2(q01[2], dup2(wa.z), h01a);
            h01b = ffma2(q01[3], dup2(wa.w), h01b);
            h23a = ffma2(q23[2], dup2(wa.z), h23a);
            h23b = ffma2(q23[3], dup2(wa.w), h23b);
            h01a = ffma2(q01[4], dup2(wb.x), h01a);
            h01b = ffma2(q01[5], dup2(wb.y), h01b);
            h23a = ffma2(q23[4], dup2(wb.x), h23a);
            h23b = ffma2(q23[5], dup2(wb.y), h23b);
            h01a = ffma2(q01[6], dup2(wb.z), h01a);
            h01b = ffma2(q01[7], dup2(wb.w), h01b);
            h23a = ffma2(q23[6], dup2(wb.z), h23a);
            h23b = ffma2(q23[7], dup2(wb.w), h23b);

            float2 h01 = fadd2(h01a, h01b);
            float2 h23 = fadd2(h23a, h23b);
            h01.x = fmaxf(h01.x, 0.0f); h01.y = fmaxf(h01.y, 0.0f);
            h23.x = fmaxf(h23.x, 0.0f); h23.y = fmaxf(h23.y, 0.0f);

            float4 va = c_w.wf[f * 4 + 2];   // w2[f][e0..3]
            float4 vb = c_w.wf[f * 4 + 3];   // w2[f][e4..7]
            float2 wp;
            wp = dup2(va.x); acc01[0] = ffma2(h01, wp, acc01[0]); acc23[0] = ffma2(h23, wp, acc23[0]);
            wp = dup2(va.y); acc01[1] = ffma2(h01, wp, acc01[1]); acc23[1] = ffma2(h23, wp, acc23[1]);
            wp = dup2(va.z); acc01[2] = ffma2(h01, wp, acc01[2]); acc23[2] = ffma2(h23, wp, acc23[2]);
            wp = dup2(va.w); acc01[3] = ffma2(h01, wp, acc01[3]); acc23[3] = ffma2(h23, wp, acc23[3]);
            wp = dup2(vb.x); acc01[4] = ffma2(h01, wp, acc01[4]); acc23[4] = ffma2(h23, wp, acc23[4]);
            wp = dup2(vb.y); acc01[5] = ffma2(h01, wp, acc01[5]); acc23[5] = ffma2(h23, wp, acc23[5]);
            wp = dup2(vb.z); acc01[6] = ffma2(h01, wp, acc01[6]); acc23[6] = ffma2(h23, wp, acc23[6]);
            wp = dup2(vb.w); acc01[7] = ffma2(h01, wp, acc01[7]); acc23[7] = ffma2(h23, wp, acc23[7]);
        }

        // store directly (no staging array)
        float4* op = reinterpret_cast<float4*>(out + row0 * EDIM);
        op[0] = make_float4(acc01[0].x, acc01[1].x, acc01[2].x, acc01[3].x);
        op[1] = make_float4(acc01[4].x, acc01[5].x, acc01[6].x, acc01[7].x);
        op[2] = make_float4(acc01[0].y, acc01[1].y, acc01[2].y, acc01[3].y);
        op[3] = make_float4(acc01[4].y, acc01[5].y, acc01[6].y, acc01[7].y);
        op[4] = make_float4(acc23[0].x, acc23[1].x, acc23[2].x, acc23[3].x);
        op[5] = make_float4(acc23[4].x, acc23[5].x, acc23[6].x, acc23[7].x);
        op[6] = make_float4(acc23[0].y, acc23[1].y, acc23[2].y, acc23[3].y);
        op[7] = make_float4(acc23[4].y, acc23[5].y, acc23[6].y, acc23[7].y);
    } else {
        // ---- tail: scalar per-row fallback ----
        for (long long r = row0; r < nrows; r++) {
            float q[EDIM];
#pragma unroll
            for (int e = 0; e < EDIM; e++) q[e] = fast_cos(x[r * EDIM + e] + th[e]);
            float o[EDIM];
#pragma unroll
            for (int e = 0; e < EDIM; e++) o[e] = c_w.b2[e];
            for (int f = 0; f < FDIM; f++) {
                float h = c_w.b1[f];
                const float* w1c = reinterpret_cast<const float*>(&c_w.wf[f * 4 + 0]);
                const float* w2r = reinterpret_cast<const float*>(&c_w.wf[f * 4 + 2]);
#pragma unroll
                for (int e = 0; e < EDIM; e++) h = fmaf(q[e], w1c[e], h);
                h = fmaxf(h, 0.0f);
#pragma unroll
                for (int e = 0; e < EDIM; e++) o[e] = fmaf(h, w2r[e], o[e]);
            }
#pragma unroll
            for (int e = 0; e < EDIM; e++) out[r * EDIM + e] = o[e];
        }
    }
}

extern "C" void kernel_launch(void* const* d_in, const int* in_sizes, int n_in,
                              void* d_out, int out_size) {
    const float* x     = (const float*)d_in[0];
    const float* theta = (const float*)d_in[1];
    const float* w1    = (const float*)d_in[2];
    const float* b1    = (const float*)d_in[3];
    const float* w2    = (const float*)d_in[4];
    const float* b2    = (const float*)d_in[5];
    float* out = (float*)d_out;

    long long nrows = (long long)in_sizes[0] / EDIM;
    long long nthreads = (nrows + RPT - 1) / RPT;
    int blocks = (int)((nthreads + BLOCK - 1) / BLOCK);

    ffq_prep<<<1, 64>>>(w1, b1, w2, b2);

    void *c_ptr = nullptr, *s_ptr = nullptr;
    cudaGetSymbolAddress(&c_ptr, c_w);
    cudaGetSymbolAddress(&s_ptr, g_s);
    cudaMemcpyAsync(c_ptr, s_ptr, sizeof(CW), cudaMemcpyDeviceToDevice, 0);

    ffq_kernel<<<blocks, BLOCK>>>(x, theta, out, nrows);
}

// round 5
// speedup vs baseline: 1.3402x; 1.3402x over previous
#include <cuda_runtime.h>

// FeedForwardQuantum: out = relu(cos(x+theta) @ W1 + b1) @ W2 + b2
// x: [524288, 8] fp32, W1: [8,32], W2: [32,8].
// R2: weights via constant port, RPT=4, 84 regs -> only 6 blocks/SM; fma 44%,
//     issue 47% -> warp-starved (latency-bound), occ 25.8%.
// R3 (failed): forcing 7 blocks via launch_bounds spilled (L1 50%, 23.7us).
// R4: RPT=2 to shrink per-thread state (~60 regs) -> 8-9 blocks/SM, ~2x warps
//     in flight; per-row FFMA2 unchanged. GEMM1 chain split 2-way for ILP.

#define EDIM 8
#define FDIM 32
#define RPT 2      // rows per thread (one f32x2 pair)
#define BLOCK 128

struct CW {
    float4 wf[FDIM * 4];  // per f: [w1col e0-3][w1col e4-7][w2row e0-3][w2row e4-7]
    float  b1[FDIM];
    float  b2[EDIM];
};

__constant__ CW c_w;     // read by main kernel via constant port
__device__   CW g_s;     // scratch filled by prep kernel, memcpy'd into c_w

// packed f32x2 ops
__device__ __forceinline__ float2 ffma2(float2 a, float2 b, float2 c) {
    float2 d;
    asm("{\n\t"
        ".reg .b64 ra, rb, rc, rd;\n\t"
        "mov.b64 ra, {%2, %3};\n\t"
        "mov.b64 rb, {%4, %5};\n\t"
        "mov.b64 rc, {%6, %7};\n\t"
        "fma.rn.f32x2 rd, ra, rb, rc;\n\t"
        "mov.b64 {%0, %1}, rd;\n\t"
        "}"
        : "=f"(d.x), "=f"(d.y)
        : "f"(a.x), "f"(a.y), "f"(b.x), "f"(b.y), "f"(c.x), "f"(c.y));
    return d;
}
__device__ __forceinline__ float2 fmul2(float2 a, float2 b) {
    float2 d;
    asm("{\n\t"
        ".reg .b64 ra, rb, rd;\n\t"
        "mov.b64 ra, {%2, %3};\n\t"
        "mov.b64 rb, {%4, %5};\n\t"
        "mul.rn.f32x2 rd, ra, rb;\n\t"
        "mov.b64 {%0, %1}, rd;\n\t"
        "}"
        : "=f"(d.x), "=f"(d.y)
        : "f"(a.x), "f"(a.y), "f"(b.x), "f"(b.y));
    return d;
}
__device__ __forceinline__ float2 fadd2(float2 a, float2 b) {
    float2 d;
    asm("{\n\t"
        ".reg .b64 ra, rb, rd;\n\t"
        "mov.b64 ra, {%2, %3};\n\t"
        "mov.b64 rb, {%4, %5};\n\t"
        "add.rn.f32x2 rd, ra, rb;\n\t"
        "mov.b64 {%0, %1}, rd;\n\t"
        "}"
        : "=f"(d.x), "=f"(d.y)
        : "f"(a.x), "f"(a.y), "f"(b.x), "f"(b.y));
    return d;
}
__device__ __forceinline__ float2 dup2(float v) { return make_float2(v, v); }

// accurate-enough cos for |a| <~ 16: 2-term 2pi reduction + MUFU cos
__device__ __forceinline__ float fast_cos(float a) {
    const float INV_2PI = 0.15915494309189535f;
    const float PI2_HI  = 6.28318548202514648f;
    const float PI2_LO  = 1.7484555e-7f;
    float k = rintf(a * INV_2PI);
    float r = fmaf(k, -PI2_HI, a);
    r = fmaf(k, PI2_LO, r);
    return __cosf(r);
}

__global__ void ffq_prep(const float* __restrict__ w1, const float* __restrict__ b1,
                         const float* __restrict__ w2, const float* __restrict__ b2)
{
    int f = threadIdx.x;
    if (f < FDIM) {
        g_s.wf[f * 4 + 0] = make_float4(w1[0 * FDIM + f], w1[1 * FDIM + f],
                                        w1[2 * FDIM + f], w1[3 * FDIM + f]);
        g_s.wf[f * 4 + 1] = make_float4(w1[4 * FDIM + f], w1[5 * FDIM + f],
                                        w1[6 * FDIM + f], w1[7 * FDIM + f]);
        const float4* w2v = reinterpret_cast<const float4*>(w2);
        g_s.wf[f * 4 + 2] = w2v[f * 2 + 0];
        g_s.wf[f * 4 + 3] = w2v[f * 2 + 1];
        g_s.b1[f] = b1[f];
        if (f < EDIM) g_s.b2[f] = b2[f];
    }
}

__global__ void __launch_bounds__(BLOCK)
ffq_kernel(const float* __restrict__ x, const float* __restrict__ theta,
           float* __restrict__ out, long long nrows)
{
    const int t = threadIdx.x;
    const long long idx  = (long long)blockIdx.x * BLOCK + t;
    const long long row0 = idx * RPT;
    if (row0 >= nrows) return;

    float th[EDIM];
#pragma unroll
    for (int e = 0; e < EDIM; e++) th[e] = __ldg(theta + e);

    if (row0 + RPT <= nrows) {
        // ---- fast path: 2 rows; q[e] = (cos row0, cos row1) ----
        const float4* xp = reinterpret_cast<const float4*>(x + row0 * EDIM);
        float4 a0 = xp[0], a1 = xp[1];   // row 0
        float4 b0 = xp[2], b1v = xp[3];  // row 1

        float2 q[EDIM];
        q[0] = make_float2(fast_cos(a0.x + th[0]), fast_cos(b0.x + th[0]));
        q[1] = make_float2(fast_cos(a0.y + th[1]), fast_cos(b0.y + th[1]));
        q[2] = make_float2(fast_cos(a0.z + th[2]), fast_cos(b0.z + th[2]));
        q[3] = make_float2(fast_cos(a0.w + th[3]), fast_cos(b0.w + th[3]));
        q[4] = make_float2(fast_cos(a1.x + th[4]), fast_cos(b1v.x + th[4]));
        q[5] = make_float2(fast_cos(a1.y + th[5]), fast_cos(b1v.y + th[5]));
        q[6] = make_float2(fast_cos(a1.z + th[6]), fast_cos(b1v.z + th[6]));
        q[7] = make_float2(fast_cos(a1.w + th[7]), fast_cos(b1v.w + th[7]));

        float2 acc[EDIM];
#pragma unroll
        for (int e = 0; e < EDIM; e++) {
            float b = c_w.b2[e];
            acc[e] = make_float2(b, b);
        }

#pragma unroll
        for (int f = 0; f < FDIM; f++) {
            float4 wa = c_w.wf[f * 4 + 0];   // w1[e0..3][f]
            float4 wb = c_w.wf[f * 4 + 1];   // w1[e4..7][f]
            float  bf = c_w.b1[f];

            // 2-way split chain (depth 4 + join)
            float2 ha = ffma2(q[0], dup2(wa.x), dup2(bf));
            float2 hb = fmul2(q[1], dup2(wa.y));
            ha = ffma2(q[2], dup2(wa.z), ha);
            hb = ffma2(q[3], dup2(wa.w), hb);
            ha = ffma2(q[4], dup2(wb.x), ha);
            hb = ffma2(q[5], dup2(wb.y), hb);
            ha = ffma2(q[6], dup2(wb.z), ha);
            hb = ffma2(q[7], dup2(wb.w), hb);
            float2 h = fadd2(ha, hb);
            h.x = fmaxf(h.x, 0.0f);
            h.y = fmaxf(h.y, 0.0f);

            float4 va = c_w.wf[f * 4 + 2];   // w2[f][e0..3]
            float4 vb = c_w.wf[f * 4 + 3];   // w2[f][e4..7]
            acc[0] = ffma2(h, dup2(va.x), acc[0]);
            acc[1] = ffma2(h, dup2(va.y), acc[1]);
            acc[2] = ffma2(h, dup2(va.z), acc[2]);
            acc[3] = ffma2(h, dup2(va.w), acc[3]);
            acc[4] = ffma2(h, dup2(vb.x), acc[4]);
            acc[5] = ffma2(h, dup2(vb.y), acc[5]);
            acc[6] = ffma2(h, dup2(vb.z), acc[6]);
            acc[7] = ffma2(h, dup2(vb.w), acc[7]);
        }

        float4* op = reinterpret_cast<float4*>(out + row0 * EDIM);
        op[0] = make_float4(acc[0].x, acc[1].x, acc[2].x, acc[3].x);
        op[1] = make_float4(acc[4].x, acc[5].x, acc[6].x, acc[7].x);
        op[2] = make_float4(acc[0].y, acc[1].y, acc[2].y, acc[3].y);
        op[3] = make_float4(acc[4].y, acc[5].y, acc[6].y, acc[7].y);
    } else {
        // ---- tail: scalar per-row fallback ----
        for (long long r = row0; r < nrows; r++) {
            float q[EDIM];
#pragma unroll
            for (int e = 0; e < EDIM; e++) q[e] = fast_cos(x[r * EDIM + e] + th[e]);
            float o[EDIM];
#pragma unroll
            for (int e = 0; e < EDIM; e++) o[e] = c_w.b2[e];
            for (int f = 0; f < FDIM; f++) {
                float h = c_w.b1[f];
                const float* w1c = reinterpret_cast<const float*>(&c_w.wf[f * 4 + 0]);
                const float* w2r = reinterpret_cast<const float*>(&c_w.wf[f * 4 + 2]);
#pragma unroll
                for (int e = 0; e < EDIM; e++) h = fmaf(q[e], w1c[e], h);
                h = fmaxf(h, 0.0f);
#pragma unroll
                for (int e = 0; e < EDIM; e++) o[e] = fmaf(h, w2r[e], o[e]);
            }
#pragma unroll
            for (int e = 0; e < EDIM; e++) out[r * EDIM + e] = o[e];
        }
    }
}

extern "C" void kernel_launch(void* const* d_in, const int* in_sizes, int n_in,
                              void* d_out, int out_size) {
    const float* x     = (const float*)d_in[0];
    const float* theta = (const float*)d_in[1];
    const float* w1    = (const float*)d_in[2];
    const float* b1    = (const float*)d_in[3];
    const float* w2    = (const float*)d_in[4];
    const float* b2    = (const float*)d_in[5];
    float* out = (float*)d_out;

    long long nrows = (long long)in_sizes[0] / EDIM;
    long long nthreads = (nrows + RPT - 1) / RPT;
    int blocks = (int)((nthreads + BLOCK - 1) / BLOCK);

    ffq_prep<<<1, 64>>>(w1, b1, w2, b2);

    void *c_ptr = nullptr, *s_ptr = nullptr;
    cudaGetSymbolAddress(&c_ptr, c_w);
    cudaGetSymbolAddress(&s_ptr, g_s);
    cudaMemcpyAsync(c_ptr, s_ptr, sizeof(CW), cudaMemcpyDeviceToDevice, 0);

    ffq_kernel<<<blocks, BLOCK>>>(x, theta, out, nrows);
}